// round 16
// baseline (speedup 1.0000x reference)
#include <cuda_runtime.h>
#include <cstdint>

// 2-layer LSTM (H=51), B=512, T=512, scalar in, linear head, future=0.
// Tensor-core tf32 mma.m16n8k8 pipeline (R15) +:
//  - A-fragments partially register-resident (S1 kf0-5, S2 kf0-4)
//  - h stored pre-rounded to tf32 (no cvt in B loads)
//  - paired B layout: float2 (k, k+4) -> 1 LDS.64 per kf, conflict-free
// 128 blocks, 832 threads: S1 = warps 0-12 (GEMM1+combine1),
// S2 = warps 13-25 (GEMM2+combine2+out). Depth-4 F/E named-barrier pipeline.

#define TT    512
#define NTH   832
#define NBLK  128
#define NIT   514
#define MT    13
#define KF1   7
#define KF2   13
#define NR1   6            // S1 reg-resident kf count
#define NR2   5            // S2 reg-resident kf count

#define OFF_A1 0
#define OFF_A2 11648             // + 13*7*32*4
#define OFF_HC 33280             // + 13*13*32*4
#define OFF_Z1 36608             // hc: 4 slots x 832
#define OFF_Z2 37440
#define OFF_X  38272
#define OFF_WL 40320
#define SMEM_FLOATS 40384
#define SMEM_BYTES (SMEM_FLOATS*4)
#define HCS 832                  // floats per hc slot: 13*32 float2 = 416*2

__device__ __forceinline__ void bar_sync_c(int id, int cnt) {
    asm volatile("bar.sync %0, %1;" :: "r"(id), "r"(cnt) : "memory");
}
__device__ __forceinline__ void bar_arrive_c(int id, int cnt) {
    asm volatile("bar.arrive %0, %1;" :: "r"(id), "r"(cnt) : "memory");
}
__device__ __forceinline__ unsigned tf32c(float x) {
    unsigned u; asm("cvt.rna.tf32.f32 %0, %1;" : "=r"(u) : "f"(x)); return u;
}
__device__ __forceinline__ void mma8(float& c0, float& c1, float& c2, float& c3,
                                     uint4 a, unsigned b0, unsigned b1) {
    asm volatile("mma.sync.aligned.m16n8k8.row.col.f32.tf32.tf32.f32 "
        "{%0,%1,%2,%3}, {%4,%5,%6,%7}, {%8,%9}, {%0,%1,%2,%3};"
        : "+f"(c0), "+f"(c1), "+f"(c2), "+f"(c3)
        : "r"(a.x), "r"(a.y), "r"(a.z), "r"(a.w), "r"(b0), "r"(b1));
}
__device__ __forceinline__ float tanhap(float x) {
    float y; asm("tanh.approx.f32 %0, %1;" : "=f"(y) : "f"(x)); return y;
}
__device__ __forceinline__ float sigap(float x) {
    return fmaf(0.5f, tanhap(0.5f * x), 0.5f);
}
// float index of h element at k-row kr, batch col cb in the pair layout
__device__ __forceinline__ int hidx(int kr, int cb) {
    return (((kr >> 3)*32 + cb*4 + (kr & 3)) << 1) + ((kr & 7) >> 2);
}

extern __shared__ float smem[];

__global__ __launch_bounds__(NTH, 1)
void lstm2_kernel(const float* __restrict__ input,
                  const float* __restrict__ W_ih1,
                  const float* __restrict__ W_hh1,
                  const float* __restrict__ b_ih1,
                  const float* __restrict__ b_hh1,
                  const float* __restrict__ W_ih2,
                  const float* __restrict__ W_hh2,
                  const float* __restrict__ b_ih2,
                  const float* __restrict__ b_hh2,
                  const float* __restrict__ W_lin,
                  const float* __restrict__ b_lin,
                  float* __restrict__ out)
{
    float* const a1f  = smem + OFF_A1;
    float* const a2f  = smem + OFF_A2;
    float* const hc   = smem + OFF_HC;   // 4 slots, pair layout (see hidx)
    float* const z1   = smem + OFF_Z1;   // [208][4]
    float* const z2   = smem + OFF_Z2;
    float* const xall = smem + OFF_X;    // [4][512]
    float* const wl   = smem + OFF_WL;   // [56]

    const int tid  = threadIdx.x;
    const int lane = tid & 31;
    const int g    = lane >> 2;
    const int tq   = lane & 3;
    const int row0 = blockIdx.x * 4;

    const bool isS1 = (tid < 416);
    const int  sw   = (isS1 ? tid : tid - 416) >> 5;
    const int  idx  = isS1 ? tid : tid - 416;
    const bool isC  = (idx < 204);
    const int  cu   = idx >> 2;
    const int  cb   = idx & 3;
    const bool isOut = (!isS1) && (idx >= 204 && idx < 212);

    // ---- stage A1 fragments (Whh1, tf32, zero-padded) ----
    for (int e = tid; e < MT*KF1*32; e += NTH) {
        const int w  = e / (KF1*32);
        const int rm = e - w*(KF1*32);
        const int kf = rm >> 5;
        const int ln = rm & 31;
        const int gg = ln >> 2, tt = ln & 3;
        const int r0 = 16*w + gg, k0 = 8*kf + tt;
        float4 v;
        v.x = (r0   < 204 && k0   < 51) ? __uint_as_float(tf32c(W_hh1[ r0   *51 + k0  ])) : 0.0f;
        v.y = (r0+8 < 204 && k0   < 51) ? __uint_as_float(tf32c(W_hh1[(r0+8)*51 + k0  ])) : 0.0f;
        v.z = (r0   < 204 && k0+4 < 51) ? __uint_as_float(tf32c(W_hh1[ r0   *51 + k0+4])) : 0.0f;
        v.w = (r0+8 < 204 && k0+4 < 51) ? __uint_as_float(tf32c(W_hh1[(r0+8)*51 + k0+4])) : 0.0f;
        reinterpret_cast<float4*>(a1f)[e] = v;
    }
    // ---- stage A2 fragments ([Wih2 | Whh2], K=102) ----
    for (int e = tid; e < MT*KF2*32; e += NTH) {
        const int w  = e / (KF2*32);
        const int rm = e - w*(KF2*32);
        const int kf = rm >> 5;
        const int ln = rm & 31;
        const int gg = ln >> 2, tt = ln & 3;
        const int r0 = 16*w + gg, k0 = 8*kf + tt;
        float4 v; float* pv = &v.x;
        #pragma unroll
        for (int q2 = 0; q2 < 4; ++q2) {
            const int r = r0 + (q2 & 1)*8;
            const int k = k0 + (q2 >> 1)*4;
            float val = 0.0f;
            if (r < 204 && k < 102)
                val = (k < 51) ? W_ih2[r*51 + k] : W_hh2[r*51 + (k - 51)];
            pv[q2] = __uint_as_float(tf32c(val));
        }
        reinterpret_cast<float4*>(a2f)[e] = v;
    }
    for (int i = tid; i < 4*HCS; i += NTH) hc[i] = 0.0f;
    for (int i = tid; i < 2*832;  i += NTH) z1[i] = 0.0f;
    for (int i = tid; i < 56;     i += NTH) wl[i] = (i < 51) ? W_lin[i] : 0.0f;
    for (int i = tid; i < 4*TT;   i += NTH) {
        const int b = i >> 9;
        const int t = i & (TT - 1);
        xall[i] = input[(row0 + b)*TT + t];
    }

    float wx[4] = {0,0,0,0}, bz[4] = {0,0,0,0};
    if (isC) {
        #pragma unroll
        for (int g4 = 0; g4 < 4; ++g4) {
            const int r = cu + 51*g4;
            if (isS1) { wx[g4] = W_ih1[r]; bz[g4] = b_ih1[r] + b_hh1[r]; }
            else      {                    bz[g4] = b_ih2[r] + b_hh2[r]; }
        }
    }
    float blin = 0.0f; int ob = 0, half = 0;
    if (isOut) { const int o = idx - 204; ob = o >> 1; half = o & 1; blin = b_lin[0]; }
    const unsigned pmask = 0x3u << (lane & 30);

    float cst = 0.0f;
    __syncthreads();   // staging complete; now load register fragments

    if (isS1) {
        // ================= S1: GEMM1 + combine1 -> h1 =================
        const float* afb = a1f + sw*(KF1*32*4);
        uint4 ar[NR1];
        #pragma unroll
        for (int kf = 0; kf < NR1; ++kf)
            ar[kf] = reinterpret_cast<const uint4*>(afb)[kf*32 + lane];
        for (int i = 0; i < NIT; ++i) {
            bar_sync_c(5 + (i & 3), NTH);
            if (i < TT) {
                const uint2* pb = reinterpret_cast<const uint2*>(hc + ((i + 3) & 3)*HCS);
                const int boff = g*4 + tq;
                float c0 = 0.f, c1 = 0.f, c2 = 0.f, c3 = 0.f;
                #pragma unroll
                for (int kf = 0; kf < NR1; ++kf) {
                    const uint2 bb = pb[kf*32 + boff];
                    mma8(c0, c1, c2, c3, ar[kf], bb.x, bb.y);
                }
                #pragma unroll
                for (int kf = NR1; kf < KF1; ++kf) {
                    const uint4 a = reinterpret_cast<const uint4*>(afb)[kf*32 + lane];
                    const uint2 bb = pb[kf*32 + boff];
                    mma8(c0, c1, c2, c3, a, bb.x, bb.y);
                }
                if (tq < 2) {
                    const int r0 = 16*sw + g;
                    *reinterpret_cast<float2*>(z1 +  r0     *4 + 2*tq) = make_float2(c0, c1);
                    *reinterpret_cast<float2*>(z1 + (r0 + 8)*4 + 2*tq) = make_float2(c2, c3);
                }
            }
            bar_sync_c(9, 416);
            if (i < TT && isC) {
                const float xv = xall[cb*TT + i];
                const float zi = z1[ cu       *4 + cb] + fmaf(xv, wx[0], bz[0]);
                const float zf = z1[(cu +  51)*4 + cb] + fmaf(xv, wx[1], bz[1]);
                const float zg = z1[(cu + 102)*4 + cb] + fmaf(xv, wx[2], bz[2]);
                const float zo = z1[(cu + 153)*4 + cb] + fmaf(xv, wx[3], bz[3]);
                const float ig = sigap(zi), fg = sigap(zf);
                const float gg = tanhap(zg), og = sigap(zo);
                cst = fmaf(fg, cst, ig*gg);
                const float hv = og * tanhap(cst);
                hc[(i & 3)*HCS + hidx(cu, cb)] = __uint_as_float(tf32c(hv));
            }
            bar_arrive_c(1 + (i & 3), NTH);
        }
    } else {
        // ================= S2: GEMM2 + combine2 -> h2; out head =================
        bar_arrive_c(5, NTH); bar_arrive_c(6, NTH);
        bar_arrive_c(7, NTH); bar_arrive_c(8, NTH);
        const float* afb = a2f + sw*(KF2*32*4);
        uint4 ar[NR2];
        #pragma unroll
        for (int kf = 0; kf < NR2; ++kf)
            ar[kf] = reinterpret_cast<const uint4*>(afb)[kf*32 + lane];
        for (int i = 0; i < NIT; ++i) {
            if (i >= 1) bar_sync_c(1 + ((i - 1) & 3), NTH);
            if (isOut && i >= 2) {
                const float* h2p = hc + ((i - 1) & 3)*HCS;
                float v = 0.f;
                #pragma unroll
                for (int m = 0; m < 26; ++m) {
                    const int j = half*26 + m;
                    if (j < 51) v = fmaf(h2p[hidx(51 + j, ob)], wl[j], v);
                }
                v += __shfl_xor_sync(pmask, v, 1);
                if (half == 0) out[(row0 + ob)*TT + (i - 2)] = v + blin;
            }
            if (i >= 1 && i <= TT) {
                const uint2* pb = reinterpret_cast<const uint2*>(hc + ((i - 1) & 3)*HCS);
                const int boff = g*4 + tq;
                float c0 = 0.f, c1 = 0.f, c2 = 0.f, c3 = 0.f;
                #pragma unroll
                for (int kf = 0; kf < NR2; ++kf) {
                    const uint2 bb = pb[kf*32 + boff];
                    mma8(c0, c1, c2, c3, ar[kf], bb.x, bb.y);
                }
                #pragma unroll
                for (int kf = NR2; kf < KF2; ++kf) {
                    const uint4 a = reinterpret_cast<const uint4*>(afb)[kf*32 + lane];
                    const uint2 bb = pb[kf*32 + boff];
                    mma8(c0, c1, c2, c3, a, bb.x, bb.y);
                }
                if (tq < 2) {
                    const int r0 = 16*sw + g;
                    *reinterpret_cast<float2*>(z2 +  r0     *4 + 2*tq) = make_float2(c0, c1);
                    *reinterpret_cast<float2*>(z2 + (r0 + 8)*4 + 2*tq) = make_float2(c2, c3);
                }
            }
            bar_sync_c(10, 416);
            if (i >= 1 && i <= TT && isC) {
                const float zi = z2[ cu       *4 + cb] + bz[0];
                const float zf = z2[(cu +  51)*4 + cb] + bz[1];
                const float zg = z2[(cu + 102)*4 + cb] + bz[2];
                const float zo = z2[(cu + 153)*4 + cb] + bz[3];
                const float ig = sigap(zi), fg = sigap(zf);
                const float gg = tanhap(zg), og = sigap(zo);
                cst = fmaf(fg, cst, ig*gg);
                const float hv = og * tanhap(cst);
                hc[(i & 3)*HCS + hidx(51 + cu, cb)] = __uint_as_float(tf32c(hv));
            }
            if (i >= 1) bar_arrive_c(5 + ((i - 1) & 3), NTH);
        }
    }
}

extern "C" void kernel_launch(void* const* d_in, const int* in_sizes, int n_in,
                              void* d_out, int out_size)
{
    const float* input = (const float*)d_in[0];
    const float* W_ih1 = (const float*)d_in[1];
    const float* W_hh1 = (const float*)d_in[2];
    const float* b_ih1 = (const float*)d_in[3];
    const float* b_hh1 = (const float*)d_in[4];
    const float* W_ih2 = (const float*)d_in[5];
    const float* W_hh2 = (const float*)d_in[6];
    const float* b_ih2 = (const float*)d_in[7];
    const float* b_hh2 = (const float*)d_in[8];
    const float* W_lin = (const float*)d_in[9];
    const float* b_lin = (const float*)d_in[10];
    float* out = (float*)d_out;

    cudaFuncSetAttribute(lstm2_kernel,
                         cudaFuncAttributeMaxDynamicSharedMemorySize, SMEM_BYTES);
    lstm2_kernel<<<NBLK, NTH, SMEM_BYTES>>>(input, W_ih1, W_hh1, b_ih1, b_hh1,
                                            W_ih2, W_hh2, b_ih2, b_hh2,
                                            W_lin, b_lin, out);
}

// round 17
// speedup vs baseline: 1.5049x; 1.5049x over previous
#include <cuda_runtime.h>
#include <cstdint>

// 2-layer LSTM (H=51), B=512, T=512, scalar in, linear head, future=0.
// Tensor-core tf32 mma.m16n8k8 pipeline (R15 structure, byte-compatible):
//   GEMM1: z1[204x4] = Whh1[204x51] x h1[51x4]
//   GEMM2: z2[204x4] = [Wih2|Whh2][204x102] x [h1(t); h2(t-1)][102x4]
// R17 deltas vs R15: (a) A-fragments kf<NR in registers (rest smem),
// (b) each GEMM uses 2 independent mma accumulator chains merged at the end.
// B loads stay R15-style: [k][8] fp32 + cvt (conflict-free). h full precision.

#define TT    512
#define NTH   832
#define NBLK  128
#define NIT   514
#define MT    13
#define KF1   7
#define KF2   13
#define NR1   6
#define NR2   5

#define OFF_A1 0
#define OFF_A2 11648
#define OFF_HC 33280
#define OFF_Z1 36608
#define OFF_Z2 37440
#define OFF_X  38272
#define OFF_WL 40320
#define SMEM_FLOATS 40384
#define SMEM_BYTES (SMEM_FLOATS*4)
#define HCS 832                  // floats per hc slot ([104][8])

__device__ __forceinline__ void bar_sync_c(int id, int cnt) {
    asm volatile("bar.sync %0, %1;" :: "r"(id), "r"(cnt) : "memory");
}
__device__ __forceinline__ void bar_arrive_c(int id, int cnt) {
    asm volatile("bar.arrive %0, %1;" :: "r"(id), "r"(cnt) : "memory");
}
__device__ __forceinline__ unsigned tf32c(float x) {
    unsigned u; asm("cvt.rna.tf32.f32 %0, %1;" : "=r"(u) : "f"(x)); return u;
}
__device__ __forceinline__ void mma8(float& c0, float& c1, float& c2, float& c3,
                                     uint4 a, unsigned b0, unsigned b1) {
    asm volatile("mma.sync.aligned.m16n8k8.row.col.f32.tf32.tf32.f32 "
        "{%0,%1,%2,%3}, {%4,%5,%6,%7}, {%8,%9}, {%0,%1,%2,%3};"
        : "+f"(c0), "+f"(c1), "+f"(c2), "+f"(c3)
        : "r"(a.x), "r"(a.y), "r"(a.z), "r"(a.w), "r"(b0), "r"(b1));
}
__device__ __forceinline__ float tanhap(float x) {
    float y; asm("tanh.approx.f32 %0, %1;" : "=f"(y) : "f"(x)); return y;
}
__device__ __forceinline__ float sigap(float x) {
    return fmaf(0.5f, tanhap(0.5f * x), 0.5f);
}

extern __shared__ float smem[];

__global__ __launch_bounds__(NTH, 1)
void lstm2_kernel(const float* __restrict__ input,
                  const float* __restrict__ W_ih1,
                  const float* __restrict__ W_hh1,
                  const float* __restrict__ b_ih1,
                  const float* __restrict__ b_hh1,
                  const float* __restrict__ W_ih2,
                  const float* __restrict__ W_hh2,
                  const float* __restrict__ b_ih2,
                  const float* __restrict__ b_hh2,
                  const float* __restrict__ W_lin,
                  const float* __restrict__ b_lin,
                  float* __restrict__ out)
{
    float* const a1f  = smem + OFF_A1;
    float* const a2f  = smem + OFF_A2;
    float* const hc   = smem + OFF_HC;   // [4][104][8]; rows 0-50 h1, 51-101 h2
    float* const z1   = smem + OFF_Z1;   // [208][4]
    float* const z2   = smem + OFF_Z2;
    float* const xall = smem + OFF_X;    // [4][512]
    float* const wl   = smem + OFF_WL;   // [56]

    const int tid  = threadIdx.x;
    const int lane = tid & 31;
    const int g    = lane >> 2;
    const int tq   = lane & 3;
    const int row0 = blockIdx.x * 4;

    const bool isS1 = (tid < 416);
    const int  sw   = (isS1 ? tid : tid - 416) >> 5;
    const int  idx  = isS1 ? tid : tid - 416;
    const bool isC  = (idx < 204);
    const int  cu   = idx >> 2;
    const int  cb   = idx & 3;
    const bool isOut = (!isS1) && (idx >= 204 && idx < 212);

    // ---- stage A1 fragments (Whh1, tf32, zero-padded) ----
    for (int e = tid; e < MT*KF1*32; e += NTH) {
        const int w  = e / (KF1*32);
        const int rm = e - w*(KF1*32);
        const int kf = rm >> 5;
        const int ln = rm & 31;
        const int gg = ln >> 2, tt = ln & 3;
        const int r0 = 16*w + gg, k0 = 8*kf + tt;
        float4 v;
        v.x = (r0   < 204 && k0   < 51) ? __uint_as_float(tf32c(W_hh1[ r0   *51 + k0  ])) : 0.0f;
        v.y = (r0+8 < 204 && k0   < 51) ? __uint_as_float(tf32c(W_hh1[(r0+8)*51 + k0  ])) : 0.0f;
        v.z = (r0   < 204 && k0+4 < 51) ? __uint_as_float(tf32c(W_hh1[ r0   *51 + k0+4])) : 0.0f;
        v.w = (r0+8 < 204 && k0+4 < 51) ? __uint_as_float(tf32c(W_hh1[(r0+8)*51 + k0+4])) : 0.0f;
        reinterpret_cast<float4*>(a1f)[e] = v;
    }
    // ---- stage A2 fragments ([Wih2 | Whh2], K=102) ----
    for (int e = tid; e < MT*KF2*32; e += NTH) {
        const int w  = e / (KF2*32);
        const int rm = e - w*(KF2*32);
        const int kf = rm >> 5;
        const int ln = rm & 31;
        const int gg = ln >> 2, tt = ln & 3;
        const int r0 = 16*w + gg, k0 = 8*kf + tt;
        float4 v; float* pv = &v.x;
        #pragma unroll
        for (int q2 = 0; q2 < 4; ++q2) {
            const int r = r0 + (q2 & 1)*8;
            const int k = k0 + (q2 >> 1)*4;
            float val = 0.0f;
            if (r < 204 && k < 102)
                val = (k < 51) ? W_ih2[r*51 + k] : W_hh2[r*51 + (k - 51)];
            pv[q2] = __uint_as_float(tf32c(val));
        }
        reinterpret_cast<float4*>(a2f)[e] = v;
    }
    for (int i = tid; i < 4*HCS; i += NTH) hc[i] = 0.0f;
    for (int i = tid; i < 2*832;  i += NTH) z1[i] = 0.0f;
    for (int i = tid; i < 56;     i += NTH) wl[i] = (i < 51) ? W_lin[i] : 0.0f;
    for (int i = tid; i < 4*TT;   i += NTH) {
        const int b = i >> 9;
        const int t = i & (TT - 1);
        xall[i] = input[(row0 + b)*TT + t];
    }

    float wx[4] = {0,0,0,0}, bz[4] = {0,0,0,0};
    if (isC) {
        #pragma unroll
        for (int g4 = 0; g4 < 4; ++g4) {
            const int r = cu + 51*g4;
            if (isS1) { wx[g4] = W_ih1[r]; bz[g4] = b_ih1[r] + b_hh1[r]; }
            else      {                    bz[g4] = b_ih2[r] + b_hh2[r]; }
        }
    }
    float blin = 0.0f; int ob = 0, half = 0;
    if (isOut) { const int o = idx - 204; ob = o >> 1; half = o & 1; blin = b_lin[0]; }
    const unsigned pmask = 0x3u << (lane & 30);

    float cst = 0.0f;
    __syncthreads();

    if (isS1) {
        // ================= S1: GEMM1 + combine1 -> h1 =================
        const float* afb = a1f + sw*(KF1*32*4);
        uint4 ar[NR1];
        #pragma unroll
        for (int kf = 0; kf < NR1; ++kf)
            ar[kf] = reinterpret_cast<const uint4*>(afb)[kf*32 + lane];
        for (int i = 0; i < NIT; ++i) {
            bar_sync_c(5 + (i & 3), NTH);
            if (i < TT) {
                const float* hin = hc + ((i + 3) & 3)*HCS;
                float c0 = 0.f, c1 = 0.f, c2 = 0.f, c3 = 0.f;
                float d0 = 0.f, d1 = 0.f, d2 = 0.f, d3 = 0.f;
                #pragma unroll
                for (int kf = 0; kf < KF1; ++kf) {
                    const uint4 a = (kf < NR1) ? ar[kf]
                        : reinterpret_cast<const uint4*>(afb)[kf*32 + lane];
                    const unsigned b0 = tf32c(hin[(8*kf + tq    )*8 + g]);
                    const unsigned b1 = tf32c(hin[(8*kf + tq + 4)*8 + g]);
                    if (kf & 1) mma8(d0, d1, d2, d3, a, b0, b1);
                    else        mma8(c0, c1, c2, c3, a, b0, b1);
                }
                c0 += d0; c1 += d1; c2 += d2; c3 += d3;
                if (tq < 2) {
                    const int r0 = 16*sw + g;
                    *reinterpret_cast<float2*>(z1 +  r0     *4 + 2*tq) = make_float2(c0, c1);
                    *reinterpret_cast<float2*>(z1 + (r0 + 8)*4 + 2*tq) = make_float2(c2, c3);
                }
            }
            bar_sync_c(9, 416);
            if (i < TT && isC) {
                const float xv = xall[cb*TT + i];
                const float zi = z1[ cu       *4 + cb] + fmaf(xv, wx[0], bz[0]);
                const float zf = z1[(cu +  51)*4 + cb] + fmaf(xv, wx[1], bz[1]);
                const float zg = z1[(cu + 102)*4 + cb] + fmaf(xv, wx[2], bz[2]);
                const float zo = z1[(cu + 153)*4 + cb] + fmaf(xv, wx[3], bz[3]);
                const float ig = sigap(zi), fg = sigap(zf);
                const float gg = tanhap(zg), og = sigap(zo);
                cst = fmaf(fg, cst, ig*gg);
                hc[(i & 3)*HCS + cu*8 + cb] = og * tanhap(cst);
            }
            bar_arrive_c(1 + (i & 3), NTH);
        }
    } else {
        // ================= S2: GEMM2 + combine2 -> h2; out head =================
        bar_arrive_c(5, NTH); bar_arrive_c(6, NTH);
        bar_arrive_c(7, NTH); bar_arrive_c(8, NTH);
        const float* afb = a2f + sw*(KF2*32*4);
        uint4 ar[NR2];
        #pragma unroll
        for (int kf = 0; kf < NR2; ++kf)
            ar[kf] = reinterpret_cast<const uint4*>(afb)[kf*32 + lane];
        for (int i = 0; i < NIT; ++i) {
            if (i >= 1) bar_sync_c(1 + ((i - 1) & 3), NTH);
            if (isOut && i >= 2) {
                const float* h2p = hc + ((i - 1) & 3)*HCS;
                float v = 0.f;
                #pragma unroll
                for (int m = 0; m < 26; ++m) {
                    const int j = half*26 + m;
                    if (j < 51) v = fmaf(h2p[(51 + j)*8 + ob], wl[j], v);
                }
                v += __shfl_xor_sync(pmask, v, 1);
                if (half == 0) out[(row0 + ob)*TT + (i - 2)] = v + blin;
            }
            if (i >= 1 && i <= TT) {
                const float* hin = hc + ((i - 1) & 3)*HCS;
                float c0 = 0.f, c1 = 0.f, c2 = 0.f, c3 = 0.f;
                float d0 = 0.f, d1 = 0.f, d2 = 0.f, d3 = 0.f;
                #pragma unroll
                for (int kf = 0; kf < KF2; ++kf) {
                    const uint4 a = (kf < NR2) ? ar[kf]
                        : reinterpret_cast<const uint4*>(afb)[kf*32 + lane];
                    const unsigned b0 = tf32c(hin[(8*kf + tq    )*8 + g]);
                    const unsigned b1 = tf32c(hin[(8*kf + tq + 4)*8 + g]);
                    if (kf & 1) mma8(d0, d1, d2, d3, a, b0, b1);
                    else        mma8(c0, c1, c2, c3, a, b0, b1);
                }
                c0 += d0; c1 += d1; c2 += d2; c3 += d3;
                if (tq < 2) {
                    const int r0 = 16*sw + g;
                    *reinterpret_cast<float2*>(z2 +  r0     *4 + 2*tq) = make_float2(c0, c1);
                    *reinterpret_cast<float2*>(z2 + (r0 + 8)*4 + 2*tq) = make_float2(c2, c3);
                }
            }
            bar_sync_c(10, 416);
            if (i >= 1 && i <= TT && isC) {
                const float zi = z2[ cu       *4 + cb] + bz[0];
                const float zf = z2[(cu +  51)*4 + cb] + bz[1];
                const float zg = z2[(cu + 102)*4 + cb] + bz[2];
                const float zo = z2[(cu + 153)*4 + cb] + bz[3];
                const float ig = sigap(zi), fg = sigap(zf);
                const float gg = tanhap(zg), og = sigap(zo);
                cst = fmaf(fg, cst, ig*gg);
                hc[(i & 3)*HCS + (51 + cu)*8 + cb] = og * tanhap(cst);
            }
            if (i >= 1) bar_arrive_c(5 + ((i - 1) & 3), NTH);
        }
    }
}

extern "C" void kernel_launch(void* const* d_in, const int* in_sizes, int n_in,
                              void* d_out, int out_size)
{
    const float* input = (const float*)d_in[0];
    const float* W_ih1 = (const float*)d_in[1];
    const float* W_hh1 = (const float*)d_in[2];
    const float* b_ih1 = (const float*)d_in[3];
    const float* b_hh1 = (const float*)d_in[4];
    const float* W_ih2 = (const float*)d_in[5];
    const float* W_hh2 = (const float*)d_in[6];
    const float* b_ih2 = (const float*)d_in[7];
    const float* b_hh2 = (const float*)d_in[8];
    const float* W_lin = (const float*)d_in[9];
    const float* b_lin = (const float*)d_in[10];
    float* out = (float*)d_out;

    cudaFuncSetAttribute(lstm2_kernel,
                         cudaFuncAttributeMaxDynamicSharedMemorySize, SMEM_BYTES);
    lstm2_kernel<<<NBLK, NTH, SMEM_BYTES>>>(input, W_ih1, W_hh1, b_ih1, b_hh1,
                                            W_ih2, W_hh2, b_ih2, b_hh2,
                                            W_lin, b_lin, out);
}